// round 7
// baseline (speedup 1.0000x reference)
#include <cuda_runtime.h>
#include <cstdint>

// ---------------- problem constants ----------------
#define Bn   32
#define Tn   3000
#define Cn   512
#define KKn  2560                 // Cin * ksize
#define BTn  (Bn*Tn)              // 96000
#define CS_SZ   (BTn*Cn)
#define MASK_OFF CS_SZ
#define LOSS_OFF (CS_SZ + BTn)

#define NCHUNK 160                // 2560 / 16
#define NB 8                      // co blocks of 64
// smem stage (floats): Ahi[128][20], Alo[128][20], Bhi[64][20], Blo[64][20]
#define ROWP 20
#define A_HI 0
#define A_LO (128*ROWP)           // 2560
#define B_HI (2*128*ROWP)         // 5120
#define B_LO (B_HI + 64*ROWP)     // 6400
#define STG_F (B_LO + 64*ROWP)    // 7680 floats = 30720 B
#define SMEM_BYTES (2*STG_F*4)    // 61440

// ---------------- scratch ----------------
__device__ float g_whi[Cn*KKn];
__device__ float g_wlo[Cn*KKn];
__device__ float g_part[NB*BTn];
__device__ float g_alpha[BTn];
__device__ float g_w1[BTn];
__device__ float g_w2[BTn];
__device__ int   g_fpos[BTn];
__device__ int   g_nfire[Bn];
__device__ int   g_tail[Bn];
__device__ float g_bsum[Bn];

// ---------------- helpers ----------------
__device__ __forceinline__ uint32_t smem_u32(const void* p) {
    uint32_t a;
    asm("{ .reg .u64 t; cvta.to.shared.u64 t, %1; cvt.u32.u64 %0, t; }"
        : "=r"(a) : "l"(p));
    return a;
}
__device__ __forceinline__ float tf32r(float x) {
    uint32_t u;
    asm("cvt.rna.tf32.f32 %0, %1;" : "=r"(u) : "f"(x));
    return __uint_as_float(u);
}
__device__ __forceinline__ void cp16(uint32_t dst, const float* src) {
    asm volatile("cp.async.cg.shared.global [%0], [%1], 16;"
                 :: "r"(dst), "l"(src));
}
__device__ __forceinline__ void mma8(float* c, uint32_t a0, uint32_t a1,
                                     uint32_t a2, uint32_t a3,
                                     uint32_t b0, uint32_t b1) {
    asm volatile(
        "mma.sync.aligned.m16n8k8.row.col.f32.tf32.tf32.f32 "
        "{%0,%1,%2,%3}, {%4,%5,%6,%7}, {%8,%9}, {%0,%1,%2,%3};"
        : "+f"(c[0]), "+f"(c[1]), "+f"(c[2]), "+f"(c[3])
        : "r"(a0), "r"(a1), "r"(a2), "r"(a3), "r"(b0), "r"(b1));
}

// ---------------- 0) weights -> tf32 hi/lo, K reordered as kr*512+ci --------
__global__ void prep_w_k(const float* __restrict__ cw) {
    int idx = blockIdx.x * blockDim.x + threadIdx.x;
    if (idx >= Cn * KKn) return;
    int co = idx / KKn;
    int kk = idx % KKn;
    int kr = kk >> 9;
    int ci = kk & 511;
    float w = cw[co * KKn + ci * 5 + kr];
    float hi = tf32r(w);
    g_whi[idx] = hi;
    g_wlo[idx] = tf32r(w - hi);
}

// ---------------- 1) conv GEMM: mma.sync tf32, 4-term split, grouped accum --
// CTA: 128 t x 64 co. 8 warps: wm=wid&3 (32 t each), wn=wid>>2 (32 co each).
__global__ void __launch_bounds__(256, 2)
conv_mma_k(const float* __restrict__ hs, const float* __restrict__ convb,
           const float* __restrict__ linw) {
    extern __shared__ float S[];
    const int tid  = threadIdx.x;
    const int wid  = tid >> 5, lane = tid & 31;
    const int g    = lane >> 2, q = lane & 3;
    const int wm   = wid & 3,  wn = wid >> 2;
    const int bx   = blockIdx.x;
    const int b    = bx / 24;
    const int tt0  = (bx % 24) * 128;
    const int cb   = blockIdx.y;
    const int co0  = cb * 64;

    const uint32_t sm0 = smem_u32(S);
    const int tA  = tid >> 1, khA = (tid & 1) * 8;   // A fill: row t, k-half
    const int tB  = tid >> 2, khB = (tid & 3) * 4;   // B fill: co row, k-quarter
    const float* wh_src = g_whi + (size_t)(co0 + tB) * KKn + khB;
    const float* wl_src = g_wlo + (size_t)(co0 + tB) * KKn + khB;

    float acc[2][4][4];     // group accumulator
    float msum[2][4][4];    // master accumulator
#pragma unroll
    for (int i = 0; i < 2; i++)
#pragma unroll
        for (int j = 0; j < 4; j++)
#pragma unroll
            for (int e = 0; e < 4; e++) { acc[i][j][e] = 0.f; msum[i][j][e] = 0.f; }

    // ---- prime stage 0 ----
    {
        const uint32_t bdst = sm0 + (B_HI + tB * ROWP + khB) * 4;
        cp16(bdst, wh_src);
        cp16(bdst + (B_LO - B_HI) * 4, wl_src);
        asm volatile("cp.async.commit_group;" ::: "memory");

        int tsrc = tt0 + tA - 2;                     // kr=0
        bool v = ((unsigned)tsrc < (unsigned)Tn);
        const float* src = hs + ((size_t)b * Tn + tsrc) * Cn + khA;
        float4 x0 = v ? *reinterpret_cast<const float4*>(src)
                      : make_float4(0.f, 0.f, 0.f, 0.f);
        float4 x1 = v ? *reinterpret_cast<const float4*>(src + 4)
                      : make_float4(0.f, 0.f, 0.f, 0.f);
        float4 h0, h1, l0, l1;
        h0.x = tf32r(x0.x); h0.y = tf32r(x0.y); h0.z = tf32r(x0.z); h0.w = tf32r(x0.w);
        h1.x = tf32r(x1.x); h1.y = tf32r(x1.y); h1.z = tf32r(x1.z); h1.w = tf32r(x1.w);
        l0.x = tf32r(x0.x - h0.x); l0.y = tf32r(x0.y - h0.y);
        l0.z = tf32r(x0.z - h0.z); l0.w = tf32r(x0.w - h0.w);
        l1.x = tf32r(x1.x - h1.x); l1.y = tf32r(x1.y - h1.y);
        l1.z = tf32r(x1.z - h1.z); l1.w = tf32r(x1.w - h1.w);
        float4* ah = reinterpret_cast<float4*>(&S[A_HI + tA * ROWP + khA]);
        float4* al = reinterpret_cast<float4*>(&S[A_LO + tA * ROWP + khA]);
        ah[0] = h0; ah[1] = h1;
        al[0] = l0; al[1] = l1;
        asm volatile("cp.async.wait_group 0;" ::: "memory");
    }
    __syncthreads();

    for (int c = 0; c < NCHUNK; c++) {
        const int st  = c & 1;
        const int nst = st ^ 1;
        const bool more = (c + 1 < NCHUNK);

        float4 x0, x1;
        if (more) {
            const int kb1 = (c + 1) * 16;
            const uint32_t bdst = sm0 + (nst * STG_F + B_HI + tB * ROWP + khB) * 4;
            cp16(bdst, wh_src + kb1);
            cp16(bdst + (B_LO - B_HI) * 4, wl_src + kb1);
            asm volatile("cp.async.commit_group;" ::: "memory");
            const int kr = kb1 >> 9, ci = kb1 & 511;
            int tsrc = tt0 + tA + kr - 2;
            bool v = ((unsigned)tsrc < (unsigned)Tn);
            const float* src = hs + ((size_t)b * Tn + tsrc) * Cn + ci + khA;
            x0 = v ? *reinterpret_cast<const float4*>(src)
                   : make_float4(0.f, 0.f, 0.f, 0.f);
            x1 = v ? *reinterpret_cast<const float4*>(src + 4)
                   : make_float4(0.f, 0.f, 0.f, 0.f);
        }

        // ---- compute current stage: 4 split terms ----
        const float* Sa_hi = S + st * STG_F + A_HI + (wm * 32 + g) * ROWP + q;
        const float* Sa_lo = S + st * STG_F + A_LO + (wm * 32 + g) * ROWP + q;
        const float* Sb_hi = S + st * STG_F + B_HI + (wn * 32 + g) * ROWP + q;
        const float* Sb_lo = S + st * STG_F + B_LO + (wn * 32 + g) * ROWP + q;
#pragma unroll
        for (int k0 = 0; k0 < 16; k0 += 8) {
            uint32_t ah[2][4], al[2][4];
#pragma unroll
            for (int mf = 0; mf < 2; mf++) {
                ah[mf][0] = __float_as_uint(Sa_hi[mf * 16 * ROWP + k0]);
                ah[mf][1] = __float_as_uint(Sa_hi[(mf * 16 + 8) * ROWP + k0]);
                ah[mf][2] = __float_as_uint(Sa_hi[mf * 16 * ROWP + k0 + 4]);
                ah[mf][3] = __float_as_uint(Sa_hi[(mf * 16 + 8) * ROWP + k0 + 4]);
                al[mf][0] = __float_as_uint(Sa_lo[mf * 16 * ROWP + k0]);
                al[mf][1] = __float_as_uint(Sa_lo[(mf * 16 + 8) * ROWP + k0]);
                al[mf][2] = __float_as_uint(Sa_lo[mf * 16 * ROWP + k0 + 4]);
                al[mf][3] = __float_as_uint(Sa_lo[(mf * 16 + 8) * ROWP + k0 + 4]);
            }
            uint32_t bh[4][2], bl[4][2];
#pragma unroll
            for (int nf = 0; nf < 4; nf++) {
                bh[nf][0] = __float_as_uint(Sb_hi[nf * 8 * ROWP + k0]);
                bh[nf][1] = __float_as_uint(Sb_hi[nf * 8 * ROWP + k0 + 4]);
                bl[nf][0] = __float_as_uint(Sb_lo[nf * 8 * ROWP + k0]);
                bl[nf][1] = __float_as_uint(Sb_lo[nf * 8 * ROWP + k0 + 4]);
            }
#pragma unroll
            for (int mf = 0; mf < 2; mf++)
#pragma unroll
                for (int nf = 0; nf < 4; nf++) {
                    mma8(acc[mf][nf], ah[mf][0], ah[mf][1], ah[mf][2], ah[mf][3],
                         bh[nf][0], bh[nf][1]);
                    mma8(acc[mf][nf], ah[mf][0], ah[mf][1], ah[mf][2], ah[mf][3],
                         bl[nf][0], bl[nf][1]);
                    mma8(acc[mf][nf], al[mf][0], al[mf][1], al[mf][2], al[mf][3],
                         bh[nf][0], bh[nf][1]);
                    mma8(acc[mf][nf], al[mf][0], al[mf][1], al[mf][2], al[mf][3],
                         bl[nf][0], bl[nf][1]);
                }
        }

        // ---- grouped drain: bound fp32 chain error ----
        if ((c & 7) == 7) {
#pragma unroll
            for (int mf = 0; mf < 2; mf++)
#pragma unroll
                for (int nf = 0; nf < 4; nf++)
#pragma unroll
                    for (int e = 0; e < 4; e++) {
                        msum[mf][nf][e] += acc[mf][nf][e];
                        acc[mf][nf][e] = 0.f;
                    }
        }

        if (more) {
            float4 h0, h1, l0, l1;
            h0.x = tf32r(x0.x); h0.y = tf32r(x0.y); h0.z = tf32r(x0.z); h0.w = tf32r(x0.w);
            h1.x = tf32r(x1.x); h1.y = tf32r(x1.y); h1.z = tf32r(x1.z); h1.w = tf32r(x1.w);
            l0.x = tf32r(x0.x - h0.x); l0.y = tf32r(x0.y - h0.y);
            l0.z = tf32r(x0.z - h0.z); l0.w = tf32r(x0.w - h0.w);
            l1.x = tf32r(x1.x - h1.x); l1.y = tf32r(x1.y - h1.y);
            l1.z = tf32r(x1.z - h1.z); l1.w = tf32r(x1.w - h1.w);
            float4* ah4 = reinterpret_cast<float4*>(
                &S[nst * STG_F + A_HI + tA * ROWP + khA]);
            float4* al4 = reinterpret_cast<float4*>(
                &S[nst * STG_F + A_LO + tA * ROWP + khA]);
            ah4[0] = h0; ah4[1] = h1;
            al4[0] = l0; al4[1] = l1;
            asm volatile("cp.async.wait_group 0;" ::: "memory");
        }
        __syncthreads();
    }

    // ---- epilogue: relu(x+bias)*lin_w, reduce over this CTA's 64 co ----
    float bias_v[4][2], lw_v[4][2];
#pragma unroll
    for (int nf = 0; nf < 4; nf++)
#pragma unroll
        for (int e = 0; e < 2; e++) {
            int cg = co0 + wn * 32 + nf * 8 + 2 * q + e;
            bias_v[nf][e] = convb[cg];
            lw_v[nf][e]   = linw[cg];
        }
    float* red = S;                              // reuse (2*128 floats)
#pragma unroll
    for (int mf = 0; mf < 2; mf++) {
#pragma unroll
        for (int h = 0; h < 2; h++) {
            float s = 0.f;
#pragma unroll
            for (int nf = 0; nf < 4; nf++)
#pragma unroll
                for (int e = 0; e < 2; e++) {
                    float x = msum[mf][nf][h * 2 + e] + bias_v[nf][e];
                    x = fmaxf(x, 0.f);
                    s = fmaf(lw_v[nf][e], x, s);
                }
            s += __shfl_xor_sync(0xffffffffu, s, 1);
            s += __shfl_xor_sync(0xffffffffu, s, 2);
            if (q == 0)
                red[wn * 128 + wm * 32 + mf * 16 + h * 8 + g] = s;
        }
    }
    __syncthreads();
    if (tid < 128) {
        float v = red[tid] + red[128 + tid];
        int t = tt0 + tid;
        if (t < Tn) g_part[cb * BTn + b * Tn + t] = v;
    }
}

// ---------------- 2) alpha = sigmoid(sum of 8 partials (fp64) + lin_b) ------
__global__ void alpha_k(const float* __restrict__ linb) {
    int idx = blockIdx.x * blockDim.x + threadIdx.x;
    if (idx >= BTn) return;
    double l = (double)linb[0];
#pragma unroll
    for (int p = 0; p < NB; p++) l += (double)g_part[p * BTn + idx];
    float lf = (float)l;
    g_alpha[idx] = 1.0f / (1.0f + expf(-lf));
}

// ---------------- 3) loss ----------------------------------------------------
__global__ void loss_a_k() {
    int b = blockIdx.x;
    __shared__ float sm[256];
    float s = 0.f;
    for (int t = threadIdx.x; t < Tn; t += 256) s += g_alpha[b * Tn + t];
    sm[threadIdx.x] = s;
    __syncthreads();
    for (int st = 128; st > 0; st >>= 1) {
        if (threadIdx.x < st) sm[threadIdx.x] += sm[threadIdx.x + st];
        __syncthreads();
    }
    if (threadIdx.x == 0) g_bsum[b] = sm[0];
}
__global__ void loss_b_k(float* out, int out_size) {
    if ((long long)out_size > LOSS_OFF) {
        float s = 0.f;
        for (int b = 0; b < Bn; b++) s += fabsf(g_bsum[b]);
        out[LOSS_OFF] = s;
    }
}

// ---------------- 4) scalar CIF scan (one warp per sequence) ----------------
__global__ void scan_k(const int* __restrict__ msk) {
    int b = blockIdx.x;
    int lane = threadIdx.x;
    float acc = 0.0f;
    int nfire = 0;
    for (int t0 = 0; t0 < Tn; t0 += 32) {
        int t = t0 + lane;
        float a = 0.f;
        if (t < Tn) {
            a = g_alpha[b * Tn + t];
            if (msk[b * Tn + t] == 0) a = 0.f;
        }
        int n = min(32, Tn - t0);
        float w1 = 0.f, w2 = 0.f;
        for (int i = 0; i < n; i++) {
            float ai = __shfl_sync(0xffffffffu, a, i);
            float acc2 = acc + ai;
            bool fired = (acc2 >= 1.0f);
            float a1 = 1.0f - acc;
            if (lane == i) {
                if (fired) { w1 = a1; w2 = ai - a1; }
                else       { w1 = ai; w2 = 0.f; }
            }
            if (fired) {
                if (lane == i) g_fpos[b * Tn + nfire] = t0 + i;
                nfire++;
                acc = ai - a1;
            } else {
                acc = acc2;
            }
        }
        if (t < Tn) { g_w1[b * Tn + t] = w1; g_w2[b * Tn + t] = w2; }
    }
    if (lane == 0) {
        g_nfire[b] = nfire;
        g_tail[b]  = (acc >= 0.5f) ? 1 : 0;
    }
}

// ---------------- 5) parallel emission ---------------------------------------
__global__ void emit_k(const float* __restrict__ hs, float* __restrict__ out,
                       int out_size) {
    int row = blockIdx.x;
    int b = row / Tn;
    int j = row % Tn;
    int nf = g_nfire[b];
    int nr = nf + g_tail[b];
    float4 accv = make_float4(0.f, 0.f, 0.f, 0.f);
    int c4 = threadIdx.x;
    const float4* hb = reinterpret_cast<const float4*>(hs) + (size_t)b * Tn * 128;
    if (j < nr) {
        int s = (j == 0) ? 0 : g_fpos[b * Tn + j - 1];
        int e = (j < nf) ? g_fpos[b * Tn + j] : (Tn - 1);
        for (int t = s; t <= e; t++) {
            float w = (t == s && j > 0) ? g_w2[b * Tn + t] : g_w1[b * Tn + t];
            float4 h = hb[(size_t)t * 128 + c4];
            accv.x = fmaf(w, h.x, accv.x);
            accv.y = fmaf(w, h.y, accv.y);
            accv.z = fmaf(w, h.z, accv.z);
            accv.w = fmaf(w, h.w, accv.w);
        }
    }
    reinterpret_cast<float4*>(out)[(size_t)row * 128 + c4] = accv;

    int nz = (accv.x != 0.f) | (accv.y != 0.f) | (accv.z != 0.f) | (accv.w != 0.f);
    __shared__ int s_any[4];
    unsigned bal = __ballot_sync(0xffffffffu, nz);
    if ((threadIdx.x & 31) == 0) s_any[threadIdx.x >> 5] = (bal != 0u);
    __syncthreads();
    if (threadIdx.x == 0) {
        int any = s_any[0] | s_any[1] | s_any[2] | s_any[3];
        if ((long long)out_size >= (long long)MASK_OFF + BTn)
            out[MASK_OFF + row] = any ? 1.0f : 0.0f;
    }
}

// ---------------- launcher ----------------------------------------------------
extern "C" void kernel_launch(void* const* d_in, const int* in_sizes, int n_in,
                              void* d_out, int out_size) {
    const float* hs  = (const float*)d_in[0];
    const int*   msk = (const int*)  d_in[1];
    const float* cw  = (const float*)d_in[2];
    const float* cb  = (const float*)d_in[3];
    const float* lw  = (const float*)d_in[4];
    const float* lb  = (const float*)d_in[5];
    float* out = (float*)d_out;

    cudaFuncSetAttribute(conv_mma_k, cudaFuncAttributeMaxDynamicSharedMemorySize,
                         SMEM_BYTES);

    prep_w_k<<<(Cn * KKn + 255) / 256, 256>>>(cw);
    conv_mma_k<<<dim3(768, NB), 256, SMEM_BYTES>>>(hs, cb, lw);
    alpha_k<<<(BTn + 255) / 256, 256>>>(lb);
    loss_a_k<<<Bn, 256>>>();
    loss_b_k<<<1, 1>>>(out, out_size);
    scan_k<<<Bn, 32>>>(msk);
    emit_k<<<BTn, 128>>>(hs, out, out_size);
}